// round 3
// baseline (speedup 1.0000x reference)
#include <cuda_runtime.h>
#include <cuda_pipeline.h>
#include <cstdint>

#define TT 512
#define BB_ 256
#define DIN 64
#define HH 256
#define GG 1024   // 4*H
#define DOUT 8

#define NB 4          // batches per CTA
#define NC (BB_/NB)   // 64 CTAs
#define CHUNK_K 8
#define NBUF 4
#define NCHUNK (HH/CHUNK_K)   // 32

// ---------------- device scratch (static, allowed) ----------------
__device__ float g_Xp[(size_t)BB_*TT*GG];   // [b][t][rr] fp32, 512MB
__device__ float g_Wt[(size_t)HH*GG];       // [k][rr] transposed+reordered W_hh (1MB)
__device__ float g_Wr_ih[(size_t)GG*DIN];   // reordered rows of W_ih
__device__ float g_br[GG];                  // reordered bias

// rr = 4*j + g  (g in order i,f,g,o), orig row = g*H + j
__global__ void reorder_whh_kernel(const float* __restrict__ W_hh) {
    int k = blockIdx.x;  // 0..255
    for (int rr = threadIdx.x; rr < GG; rr += blockDim.x) {
        int jj = rr >> 2, g = rr & 3;
        g_Wt[(size_t)k * GG + rr] = W_hh[(size_t)(g * HH + jj) * HH + k];
    }
}

__global__ void reorder_wih_kernel(const float* __restrict__ W_ih,
                                   const float* __restrict__ bias) {
    int rr = blockIdx.x;
    int jj = rr >> 2, g = rr & 3;
    int orig = g * HH + jj;
    if (threadIdx.x < DIN)
        g_Wr_ih[(size_t)rr * DIN + threadIdx.x] = W_ih[(size_t)orig * DIN + threadIdx.x];
    if (threadIdx.x == 0) g_br[rr] = bias[orig];
}

// ---------------- input projection GEMM ----------------
// Xp[m][rr] = sum_k x[m][k] * Wr_ih[rr][k] + br[rr],  m = b*T + t
// tile 64m x 64n, K=64 full. 256 threads, 4x4 outputs per thread.
__global__ void __launch_bounds__(256) xproj_kernel(const float* __restrict__ x) {
    __shared__ float As[DIN][68];   // [k][m]
    __shared__ float Bs[DIN][68];   // [k][n]
    int m0 = blockIdx.x * 64, n0 = blockIdx.y * 64;
    int tid = threadIdx.x;

    for (int i = tid; i < 1024; i += 256) {
        int r  = i >> 4;       // row 0..63
        int kq = i & 15;       // float4 index within 64 k
        float4 v = ((const float4*)(x + (size_t)(m0 + r) * DIN))[kq];
        As[kq*4+0][r] = v.x; As[kq*4+1][r] = v.y; As[kq*4+2][r] = v.z; As[kq*4+3][r] = v.w;
        float4 w = ((const float4*)(g_Wr_ih + (size_t)(n0 + r) * DIN))[kq];
        Bs[kq*4+0][r] = w.x; Bs[kq*4+1][r] = w.y; Bs[kq*4+2][r] = w.z; Bs[kq*4+3][r] = w.w;
    }
    __syncthreads();

    int tm = (tid >> 4) << 2;
    int tn = (tid & 15) << 2;
    float acc[4][4] = {};
    #pragma unroll 8
    for (int k = 0; k < DIN; k++) {
        float a[4], b[4];
        *(float4*)a = *(const float4*)&As[k][tm];
        *(float4*)b = *(const float4*)&Bs[k][tn];
        #pragma unroll
        for (int i = 0; i < 4; i++)
            #pragma unroll
            for (int jj = 0; jj < 4; jj++)
                acc[i][jj] += a[i] * b[jj];
    }
    float4 bias = *(const float4*)(g_br + n0 + tn);
    #pragma unroll
    for (int i = 0; i < 4; i++) {
        float4 r;
        r.x = acc[i][0] + bias.x; r.y = acc[i][1] + bias.y;
        r.z = acc[i][2] + bias.z; r.w = acc[i][3] + bias.w;
        *(float4*)(g_Xp + (size_t)(m0 + tm + i) * GG + n0 + tn) = r;
    }
}

// ---------------- LSTM recurrence ----------------
#define FMA2(acc, a, b) asm("fma.rn.f32x2 %0, %1, %2, %0;" : "+l"(acc) : "l"(a), "l"(b))

__device__ __forceinline__ float lof(unsigned long long v) { return __uint_as_float((unsigned)v); }
__device__ __forceinline__ float hif(unsigned long long v) { return __uint_as_float((unsigned)(v >> 32)); }
__device__ __forceinline__ unsigned long long dupf(float f) {
    unsigned u = __float_as_uint(f);
    return (unsigned long long)u | ((unsigned long long)u << 32);
}
__device__ __forceinline__ float sigf(float x)  { return 1.f / (1.f + __expf(-x)); }
__device__ __forceinline__ float tanhf_fast(float x) { return 2.f / (1.f + __expf(-2.f * x)) - 1.f; }

__device__ __forceinline__ void stage_chunk(float* w_buf, int buf, int k0, int tid) {
    const float4* src = (const float4*)(g_Wt + (size_t)k0 * GG);
    float4* dst = (float4*)(w_buf + (size_t)buf * CHUNK_K * GG);
    #pragma unroll
    for (int i = 0; i < (CHUNK_K * GG / 4) / 256; i++)   // 8 x 16B per thread
        __pipeline_memcpy_async(dst + tid + i * 256, src + tid + i * 256, 16);
    __pipeline_commit();
}

__global__ void __launch_bounds__(256, 1) lstm_kernel(const float* __restrict__ h0,
                                                      const float* __restrict__ c0,
                                                      float* __restrict__ out) {
    extern __shared__ char smem[];
    float* w_buf = (float*)smem;                                           // [NBUF][CHUNK_K][GG]
    unsigned long long* sh_h =
        (unsigned long long*)(smem + (size_t)NBUF * CHUNK_K * GG * 4);     // [2][HH][NB], dup'd

    const int tid = threadIdx.x;
    const int j   = tid;                 // h index 0..255
    const int b0  = blockIdx.x * NB;

    float c[NB], hlast[NB];
    #pragma unroll
    for (int bb = 0; bb < NB; bb++) {
        c[bb] = c0[(size_t)(b0 + bb) * HH + j];
        float hv = h0[(size_t)(b0 + bb) * HH + j];
        hlast[bb] = hv;
        sh_h[(size_t)j * NB + bb] = dupf(hv);
    }

    stage_chunk(w_buf, 0, 0, tid);
    stage_chunk(w_buf, 1, CHUNK_K, tid);
    stage_chunk(w_buf, 2, 2 * CHUNK_K, tid);
    __syncthreads();

    int cur = 0;
    for (int t = 0; t < TT; t++) {
        unsigned long long acc[2][NB];
        #pragma unroll
        for (int bb = 0; bb < NB; bb++) {
            ulonglong2 xv = *(const ulonglong2*)(g_Xp + ((size_t)(b0 + bb) * TT + t) * GG + 4 * j);
            acc[0][bb] = xv.x;   // gates (i,f)
            acc[1][bb] = xv.y;   // gates (g,o)
        }

        #pragma unroll 1
        for (int ch = 0; ch < NCHUNK; ch++) {
            __pipeline_wait_prior(2);
            __syncthreads();
            int nc = ch + 3; if (nc >= NCHUNK) nc -= NCHUNK;
            stage_chunk(w_buf, (ch + 3) & 3, nc * CHUNK_K, tid);

            const float* wb = w_buf + (size_t)(ch & 3) * CHUNK_K * GG;
            const unsigned long long* hb =
                sh_h + (size_t)cur * HH * NB + (size_t)ch * CHUNK_K * NB;
            #pragma unroll
            for (int kk = 0; kk < CHUNK_K; kk++) {
                ulonglong2 w    = *(const ulonglong2*)(wb + (size_t)kk * GG + 4 * j);
                ulonglong2 hd01 = *(const ulonglong2*)(hb + kk * NB);
                ulonglong2 hd23 = *(const ulonglong2*)(hb + kk * NB + 2);
                FMA2(acc[0][0], w.x, hd01.x); FMA2(acc[1][0], w.y, hd01.x);
                FMA2(acc[0][1], w.x, hd01.y); FMA2(acc[1][1], w.y, hd01.y);
                FMA2(acc[0][2], w.x, hd23.x); FMA2(acc[1][2], w.y, hd23.x);
                FMA2(acc[0][3], w.x, hd23.y); FMA2(acc[1][3], w.y, hd23.y);
            }
        }

        int nxt = cur ^ 1;
        unsigned long long* hw = sh_h + (size_t)nxt * HH * NB + (size_t)j * NB;
        #pragma unroll
        for (int bb = 0; bb < NB; bb++) {
            float ip = lof(acc[0][bb]), fp = hif(acc[0][bb]);
            float gp = lof(acc[1][bb]), op = hif(acc[1][bb]);
            float ig = sigf(ip), fg = sigf(fp), og = sigf(op);
            float gg = tanhf_fast(gp);
            c[bb] = fg * c[bb] + ig * gg;
            float hn = og * tanhf_fast(c[bb]);
            hlast[bb] = hn;
            hw[bb] = dupf(hn);
        }
        cur = nxt;
        // no extra barrier: next chunk-0 __syncthreads orders these writes
    }

    // outputs: rnn_outputs @0, logits @65536, h @67584, c @133120
    #pragma unroll
    for (int bb = 0; bb < NB; bb++) {
        size_t idx = (size_t)(b0 + bb) * HH + j;
        out[idx]           = hlast[bb];
        out[67584 + idx]   = hlast[bb];
        out[133120 + idx]  = c[bb];
    }
}

// ---------------- output projection ----------------
__global__ void logits_kernel(const float* __restrict__ hbase,
                              const float* __restrict__ W_out,
                              const float* __restrict__ b_out,
                              float* __restrict__ out_logits) {
    int b = blockIdx.x;
    int d = threadIdx.x >> 5;     // 8 warps = 8 outputs
    int lane = threadIdx.x & 31;
    const float* hr = hbase + (size_t)b * HH;
    const float* wr = W_out + (size_t)d * HH;
    float s = 0.f;
    #pragma unroll
    for (int k = lane; k < HH; k += 32) s += hr[k] * wr[k];
    #pragma unroll
    for (int o = 16; o; o >>= 1) s += __shfl_down_sync(0xffffffffu, s, o);
    if (lane == 0) out_logits[b * DOUT + d] = s + b_out[d];
}

// ---------------- launch ----------------
extern "C" void kernel_launch(void* const* d_in, const int* in_sizes, int n_in,
                              void* d_out, int out_size) {
    const float* x     = (const float*)d_in[0];
    const float* h0    = (const float*)d_in[1];
    const float* c0    = (const float*)d_in[2];
    const float* W_ih  = (const float*)d_in[3];
    const float* W_hh  = (const float*)d_in[4];
    const float* bias  = (const float*)d_in[5];
    const float* W_out = (const float*)d_in[6];
    const float* b_out = (const float*)d_in[7];
    float* out = (float*)d_out;

    reorder_whh_kernel<<<HH, 256>>>(W_hh);
    reorder_wih_kernel<<<GG, 64>>>(W_ih, bias);

    xproj_kernel<<<dim3((BB_ * TT) / 64, GG / 64), 256>>>(x);

    size_t smem_bytes = (size_t)NBUF * CHUNK_K * GG * 4 + (size_t)2 * HH * NB * 8; // 147456
    cudaFuncSetAttribute(lstm_kernel, cudaFuncAttributeMaxDynamicSharedMemorySize,
                         (int)smem_bytes);
    lstm_kernel<<<NC, 256, smem_bytes>>>(h0, c0, out);

    logits_kernel<<<BB_, 256>>>(out, W_out, b_out, out + 65536);
}

// round 5
// speedup vs baseline: 1.1010x; 1.1010x over previous
#include <cuda_runtime.h>
#include <cstdint>

typedef unsigned long long ull;

#define TT 512
#define BB_ 256
#define DIN 64
#define HH 256
#define GG 1024   // 4*H
#define DOUT 8

#define CL 8            // CTAs per cluster
#define NCLUST 16       // clusters
#define NBC 16          // batches per cluster
#define NCTA (NCLUST*CL)

// ---------------- device scratch (static, allowed) ----------------
__device__ __align__(128) float g_Xp[(size_t)BB_*TT*GG];   // [b][t][rr]
__device__ __align__(128) float g_Wt[(size_t)HH*GG];       // [k][rr] reordered W_hh
__device__ __align__(128) float g_Wr_ih[(size_t)GG*DIN];
__device__ __align__(128) float g_br[GG];
__device__ __align__(128) ull   g_hex[(size_t)NCLUST*HH*NBC]; // [cl][k][b] dup'd h

// ---------------- helpers ----------------
__device__ __forceinline__ ull dupf(float f){ unsigned u=__float_as_uint(f); return (ull)u | ((ull)u<<32); }
__device__ __forceinline__ float lof(ull v){ return __uint_as_float((unsigned)v); }
__device__ __forceinline__ float hif(ull v){ return __uint_as_float((unsigned)(v>>32)); }
#define FMA2(acc,a,b) asm("fma.rn.f32x2 %0, %1, %2, %0;" : "+l"(acc) : "l"(a), "l"(b))
__device__ __forceinline__ float sigf(float x){ return __fdividef(1.f, 1.f + __expf(-x)); }
__device__ __forceinline__ float thf(float x){ return __fdividef(2.f, 1.f + __expf(-2.f*x)) - 1.f; }

#define CP16(dst_s, src_g) \
    asm volatile("cp.async.cg.shared.global [%0], [%1], 16;" :: "r"(dst_s), "l"(src_g) : "memory")
#define CP_COMMIT()  asm volatile("cp.async.commit_group;" ::: "memory")
#define CP_WAIT(n)   asm volatile("cp.async.wait_group %0;" :: "n"(n) : "memory")
#define CLUSTER_SYNC() do { \
    asm volatile("barrier.cluster.arrive.aligned;" ::: "memory"); \
    asm volatile("barrier.cluster.wait.aligned;"   ::: "memory"); } while(0)

// ---------------- weight reorder (one-time) ----------------
// rr = 4*j + g  (g in order i,f,g,o), orig row = g*H + j
__global__ void reorder_whh_kernel(const float* __restrict__ W_hh) {
    int k = blockIdx.x;
    for (int rr = threadIdx.x; rr < GG; rr += blockDim.x) {
        int jj = rr >> 2, g = rr & 3;
        g_Wt[(size_t)k * GG + rr] = W_hh[(size_t)(g * HH + jj) * HH + k];
    }
}

__global__ void reorder_wih_kernel(const float* __restrict__ W_ih,
                                   const float* __restrict__ bias) {
    int rr = blockIdx.x;
    int jj = rr >> 2, g = rr & 3;
    int orig = g * HH + jj;
    if (threadIdx.x < DIN)
        g_Wr_ih[(size_t)rr * DIN + threadIdx.x] = W_ih[(size_t)orig * DIN + threadIdx.x];
    if (threadIdx.x == 0) g_br[rr] = bias[orig];
}

// ---------------- input projection GEMM ----------------
__global__ void __launch_bounds__(256) xproj_kernel(const float* __restrict__ x) {
    __shared__ float As[DIN][68];
    __shared__ float Bs[DIN][68];
    int m0 = blockIdx.x * 64, n0 = blockIdx.y * 64;
    int tid = threadIdx.x;

    for (int i = tid; i < 1024; i += 256) {
        int r  = i >> 4;
        int kq = i & 15;
        float4 v = ((const float4*)(x + (size_t)(m0 + r) * DIN))[kq];
        As[kq*4+0][r] = v.x; As[kq*4+1][r] = v.y; As[kq*4+2][r] = v.z; As[kq*4+3][r] = v.w;
        float4 w = ((const float4*)(g_Wr_ih + (size_t)(n0 + r) * DIN))[kq];
        Bs[kq*4+0][r] = w.x; Bs[kq*4+1][r] = w.y; Bs[kq*4+2][r] = w.z; Bs[kq*4+3][r] = w.w;
    }
    __syncthreads();

    int tm = (tid >> 4) << 2;
    int tn = (tid & 15) << 2;
    float acc[4][4] = {};
    #pragma unroll 8
    for (int k = 0; k < DIN; k++) {
        float a[4], b[4];
        *(float4*)a = *(const float4*)&As[k][tm];
        *(float4*)b = *(const float4*)&Bs[k][tn];
        #pragma unroll
        for (int i = 0; i < 4; i++)
            #pragma unroll
            for (int jj = 0; jj < 4; jj++)
                acc[i][jj] += a[i] * b[jj];
    }
    float4 bias = *(const float4*)(g_br + n0 + tn);
    #pragma unroll
    for (int i = 0; i < 4; i++) {
        float4 r;
        r.x = acc[i][0] + bias.x; r.y = acc[i][1] + bias.y;
        r.z = acc[i][2] + bias.z; r.w = acc[i][3] + bias.w;
        *(float4*)(g_Xp + (size_t)(m0 + tm + i) * GG + n0 + tn) = r;
    }
}

// ---------------- LSTM recurrence: cluster-resident W ----------------
// smem layout (dynamic):
//   sh_h  : ull [256][16]          32KB   (dup'd h, all k, cluster batches)
//   red   : ull [16][4][64]        32KB   (partial gate sums [b][kq][rrp])
//   xbuf  : float [2][16][128]     16KB   (Xp slice double buffer)
#define SH_H_ULL   (HH*NBC)          // 4096
#define RED_ULL    (NBC*4*64)        // 4096
#define XBUF_F     (2*NBC*128)       // 4096
#define LSTM_SMEM  (SH_H_ULL*8 + RED_ULL*8 + XBUF_F*4)   // 81920

__global__ void __launch_bounds__(256, 1) __cluster_dims__(CL, 1, 1)
lstm_kernel(const float* __restrict__ h0, const float* __restrict__ c0,
            float* __restrict__ out) {
    extern __shared__ __align__(16) char smem[];
    ull*   sh_h = (ull*)smem;                               // [k][b]
    ull*   red  = sh_h + SH_H_ULL;                          // [b][kq][rrp]
    float* xbuf = (float*)(red + RED_ULL);                  // [buf][b][128]

    const int tid   = threadIdx.x;
    const int slice = blockIdx.x & (CL - 1);                // cluster rank
    const int cl    = blockIdx.x >> 3;                      // cluster id
    const int b0c   = cl * NBC;
    const int kq    = tid >> 6;                             // k quarter (64 k)
    const int rrp   = tid & 63;                             // rr-pair within slice
    const int rrbase = slice * 128 + 2 * rrp;               // global rr of pair

    // epilogue mapping (fixed per thread across steps)
    const int ej  = tid & 31;                               // local j (0..31)
    const int ebp = tid >> 5;                               // batch pair (0..7)
    const int eb0 = 2 * ebp;

    // ---- prologue ----
    // resident weights: wreg[kk] = (W[k][rr0], W[k][rr1]), k = kq*64+kk
    ull wreg[64];
    #pragma unroll
    for (int kk = 0; kk < 64; kk++)
        wreg[kk] = *(const ull*)(g_Wt + (size_t)(kq * 64 + kk) * GG + rrbase);

    // init sh_h from h0 (dup'd)
    {
        int k = tid;
        #pragma unroll
        for (int b = 0; b < NBC; b++)
            sh_h[k * NBC + b] = dupf(h0[(size_t)(b0c + b) * HH + k]);
    }
    // c state in epilogue threads
    float creg[2], hlast[2];
    #pragma unroll
    for (int q = 0; q < 2; q++)
        creg[q] = c0[(size_t)(b0c + eb0 + q) * HH + slice * 32 + ej];

    // prefetch Xp slice for t=0 into xbuf[0]
    {
        unsigned dst = (unsigned)__cvta_generic_to_shared(
            xbuf + (size_t)(tid >> 4) * 128 + (tid & 15) * 8);
        const float* src = g_Xp + ((size_t)(b0c + (tid >> 4)) * TT + 0) * GG
                           + slice * 128 + (tid & 15) * 8;
        CP16(dst, src); CP16(dst + 16, src + 4);
        CP_COMMIT();
    }
    __syncthreads();

    // ---- time loop ----
    for (int t = 0; t < TT; t++) {
        CP_WAIT(1);             // h-fill (prev step) done; x may still fly
        __syncthreads();

        // FMA mainloop over this thread's k-quarter
        ull acc[NBC];
        #pragma unroll
        for (int b = 0; b < NBC; b++) acc[b] = 0ull;

        const ull* hq = sh_h + (size_t)kq * 64 * NBC;
        #pragma unroll
        for (int kk = 0; kk < 64; kk++) {
            const ulonglong2* hp = (const ulonglong2*)(hq + kk * NBC);
            #pragma unroll
            for (int p = 0; p < 8; p++) {
                ulonglong2 h2 = hp[p];
                FMA2(acc[2*p  ], wreg[kk], h2.x);
                FMA2(acc[2*p+1], wreg[kk], h2.y);
            }
        }

        // write partials: red[b][kq][rrp]
        #pragma unroll
        for (int b = 0; b < NBC; b++)
            red[(b * 4 + kq) * 64 + rrp] = acc[b];

        CP_WAIT(0);             // x(t) ready
        __syncthreads();        // red + xbuf visible

        // epilogue: thread owns (j=ej, batches eb0,eb0+1)
        ull hnew2;
        {
            float hv[2];
            #pragma unroll
            for (int q = 0; q < 2; q++) {
                int b = eb0 + q;
                const ulonglong2* rp = (const ulonglong2*)(red + (b * 4) * 64 + 2 * ej);
                ulonglong2 s0 = rp[0], s1 = rp[32], s2 = rp[64], s3 = rp[96]; // kq stride = 64 ull /2
                ull sif, sgo;
                asm("add.rn.f32x2 %0, %1, %2;" : "=l"(sif) : "l"(s0.x), "l"(s1.x));
                asm("add.rn.f32x2 %0, %0, %1;" : "+l"(sif) : "l"(s2.x));
                asm("add.rn.f32x2 %0, %0, %1;" : "+l"(sif) : "l"(s3.x));
                asm("add.rn.f32x2 %0, %1, %2;" : "=l"(sgo) : "l"(s0.y), "l"(s1.y));
                asm("add.rn.f32x2 %0, %0, %1;" : "+l"(sgo) : "l"(s2.y));
                asm("add.rn.f32x2 %0, %0, %1;" : "+l"(sgo) : "l"(s3.y));
                float4 xv = *(const float4*)(xbuf + ((size_t)(t & 1) * NBC + b) * 128 + 4 * ej);
                float ig = sigf(xv.x + lof(sif));
                float fg = sigf(xv.y + hif(sif));
                float gg = thf (xv.z + lof(sgo));
                float og = sigf(xv.w + hif(sgo));
                creg[q] = fg * creg[q] + ig * gg;
                hv[q]   = og * thf(creg[q]);
                hlast[q] = hv[q];
            }
            ull lo = dupf(hv[0]), hi = dupf(hv[1]);
            hnew2 = lo; // silence unused
            // publish dup'd h pair to global exchange buffer
            ulonglong2 pk; pk.x = lo; pk.y = hi;
            *(ulonglong2*)(g_hex + ((size_t)cl * HH + slice * 32 + ej) * NBC + eb0) = pk;
            (void)hnew2;
        }

        if (t < TT - 1) {
            __threadfence();
            CLUSTER_SYNC();
            // h-fill: copy full cluster h (32KB) into sh_h
            {
                unsigned dst = (unsigned)__cvta_generic_to_shared((char*)sh_h + tid * 128);
                const char* src = (const char*)(g_hex + (size_t)cl * HH * NBC) + tid * 128;
                #pragma unroll
                for (int i = 0; i < 8; i++) CP16(dst + i * 16, src + i * 16);
                CP_COMMIT();
            }
            // x prefetch for t+1
            {
                unsigned dst = (unsigned)__cvta_generic_to_shared(
                    xbuf + ((size_t)((t + 1) & 1) * NBC + (tid >> 4)) * 128 + (tid & 15) * 8);
                const float* src = g_Xp + ((size_t)(b0c + (tid >> 4)) * TT + (t + 1)) * GG
                                   + slice * 128 + (tid & 15) * 8;
                CP16(dst, src); CP16(dst + 16, src + 4);
                CP_COMMIT();
            }
        }
    }

    // ---- outputs: rnn_outputs @0, logits @65536, h @67584, c @133120 ----
    #pragma unroll
    for (int q = 0; q < 2; q++) {
        size_t idx = (size_t)(b0c + eb0 + q) * HH + slice * 32 + ej;
        out[idx]          = hlast[q];
        out[67584 + idx]  = hlast[q];
        out[133120 + idx] = creg[q];
    }
}

// ---------------- output projection ----------------
__global__ void logits_kernel(const float* __restrict__ hbase,
                              const float* __restrict__ W_out,
                              const float* __restrict__ b_out,
                              float* __restrict__ out_logits) {
    int b = blockIdx.x;
    int d = threadIdx.x >> 5;
    int lane = threadIdx.x & 31;
    const float* hr = hbase + (size_t)b * HH;
    const float* wr = W_out + (size_t)d * HH;
    float s = 0.f;
    #pragma unroll
    for (int k = lane; k < HH; k += 32) s += hr[k] * wr[k];
    #pragma unroll
    for (int o = 16; o; o >>= 1) s += __shfl_down_sync(0xffffffffu, s, o);
    if (lane == 0) out_logits[b * DOUT + d] = s + b_out[d];
}

// ---------------- launch ----------------
extern "C" void kernel_launch(void* const* d_in, const int* in_sizes, int n_in,
                              void* d_out, int out_size) {
    const float* x     = (const float*)d_in[0];
    const float* h0    = (const float*)d_in[1];
    const float* c0    = (const float*)d_in[2];
    const float* W_ih  = (const float*)d_in[3];
    const float* W_hh  = (const float*)d_in[4];
    const float* bias  = (const float*)d_in[5];
    const float* W_out = (const float*)d_in[6];
    const float* b_out = (const float*)d_in[7];
    float* out = (float*)d_out;

    reorder_whh_kernel<<<HH, 256>>>(W_hh);
    reorder_wih_kernel<<<GG, 64>>>(W_ih, bias);

    xproj_kernel<<<dim3((BB_ * TT) / 64, GG / 64), 256>>>(x);

    static int cfg_done = 0;
    if (!cfg_done) {
        cudaFuncSetAttribute(lstm_kernel, cudaFuncAttributeMaxDynamicSharedMemorySize,
                             LSTM_SMEM);
        cfg_done = 1;
    }
    lstm_kernel<<<NCTA, 256, LSTM_SMEM>>>(h0, c0, out);

    logits_kernel<<<BB_, 256>>>(out, W_out, b_out, out + 65536);
}

// round 6
// speedup vs baseline: 1.1531x; 1.0473x over previous
#include <cuda_runtime.h>
#include <cstdint>

typedef unsigned long long ull;

#define TT 512
#define BB_ 256
#define DIN 64
#define HH 256
#define GG 1024   // 4*H
#define DOUT 8

#define CL 8            // CTAs per cluster
#define NCLUST 16       // clusters
#define NBC 16          // batches per cluster
#define NCTA (NCLUST*CL)
#define NT 512          // threads per lstm CTA

// ---------------- device scratch (static, allowed) ----------------
__device__ __align__(128) float g_Xp[(size_t)BB_*TT*GG];   // [b][t][rr]
__device__ __align__(128) float g_Wt[(size_t)HH*GG];       // [k][rr] reordered W_hh
__device__ __align__(128) float g_Wr_ih[(size_t)GG*DIN];
__device__ __align__(128) float g_br[GG];
__device__ __align__(128) ull   g_hex[(size_t)NCLUST*NBC*HH]; // [cl][b][k] dup'd h

// ---------------- helpers ----------------
__device__ __forceinline__ ull dupf(float f){ unsigned u=__float_as_uint(f); return (ull)u | ((ull)u<<32); }
__device__ __forceinline__ float lof(ull v){ return __uint_as_float((unsigned)v); }
__device__ __forceinline__ float hif(ull v){ return __uint_as_float((unsigned)(v>>32)); }
#define FMA2(acc,a,b) asm("fma.rn.f32x2 %0, %1, %2, %0;" : "+l"(acc) : "l"(a), "l"(b))
#define ADD2(d,a,b)   asm("add.rn.f32x2 %0, %1, %2;" : "=l"(d) : "l"(a), "l"(b))
__device__ __forceinline__ float sigf(float x){ return __fdividef(1.f, 1.f + __expf(-x)); }
__device__ __forceinline__ float thf(float x){ return __fdividef(2.f, 1.f + __expf(-2.f*x)) - 1.f; }

#define CP16(dst_s, src_g) \
    asm volatile("cp.async.cg.shared.global [%0], [%1], 16;" :: "r"(dst_s), "l"(src_g) : "memory")
#define CP_COMMIT()  asm volatile("cp.async.commit_group;" ::: "memory")
#define CP_WAIT(n)   asm volatile("cp.async.wait_group %0;" :: "n"(n) : "memory")
#define CLUSTER_SYNC() do { \
    asm volatile("barrier.cluster.arrive.aligned;" ::: "memory"); \
    asm volatile("barrier.cluster.wait.aligned;"   ::: "memory"); } while(0)

// ---------------- weight reorder (one-time) ----------------
// rr = 4*j + g  (g in order i,f,g,o), orig row = g*H + j
__global__ void reorder_whh_kernel(const float* __restrict__ W_hh) {
    int k = blockIdx.x;
    for (int rr = threadIdx.x; rr < GG; rr += blockDim.x) {
        int jj = rr >> 2, g = rr & 3;
        g_Wt[(size_t)k * GG + rr] = W_hh[(size_t)(g * HH + jj) * HH + k];
    }
}

__global__ void reorder_wih_kernel(const float* __restrict__ W_ih,
                                   const float* __restrict__ bias) {
    int rr = blockIdx.x;
    int jj = rr >> 2, g = rr & 3;
    int orig = g * HH + jj;
    if (threadIdx.x < DIN)
        g_Wr_ih[(size_t)rr * DIN + threadIdx.x] = W_ih[(size_t)orig * DIN + threadIdx.x];
    if (threadIdx.x == 0) g_br[rr] = bias[orig];
}

// ---------------- input projection GEMM (f32x2) ----------------
// Xp[m][rr] = sum_k x[m][k] * Wr_ih[rr][k] + br[rr]
// tile 64m x 64n, K=64 full. 256 threads, each 4m x 4n via packed f32x2.
__global__ void __launch_bounds__(256) xproj_kernel(const float* __restrict__ x) {
    __shared__ ull   As2[DIN][66];   // dup'd x: As2[k][m], row stride 528B (16B mult)
    __shared__ float Bs [DIN][68];   // W: Bs[k][n], row stride 272B (16B mult)
    int m0 = blockIdx.x * 64, n0 = blockIdx.y * 64;
    int tid = threadIdx.x;

    for (int i = tid; i < 1024; i += 256) {
        int r  = i >> 4;       // row 0..63
        int kq = i & 15;       // float4 index within 64 k
        float4 v = ((const float4*)(x + (size_t)(m0 + r) * DIN))[kq];
        As2[kq*4+0][r] = dupf(v.x); As2[kq*4+1][r] = dupf(v.y);
        As2[kq*4+2][r] = dupf(v.z); As2[kq*4+3][r] = dupf(v.w);
        float4 w = ((const float4*)(g_Wr_ih + (size_t)(n0 + r) * DIN))[kq];
        Bs[kq*4+0][r] = w.x; Bs[kq*4+1][r] = w.y; Bs[kq*4+2][r] = w.z; Bs[kq*4+3][r] = w.w;
    }
    __syncthreads();

    int tm = (tid >> 4) << 2;     // 4 m rows
    int tn = (tid & 15) << 2;     // 4 n cols (2 f32x2 pairs)
    ull acc2[4][2] = {};
    #pragma unroll 8
    for (int k = 0; k < DIN; k++) {
        ulonglong2 a01 = *(const ulonglong2*)&As2[k][tm];
        ulonglong2 a23 = *(const ulonglong2*)&As2[k][tm + 2];
        ulonglong2 b2  = *(const ulonglong2*)&Bs[k][tn];
        FMA2(acc2[0][0], a01.x, b2.x); FMA2(acc2[0][1], a01.x, b2.y);
        FMA2(acc2[1][0], a01.y, b2.x); FMA2(acc2[1][1], a01.y, b2.y);
        FMA2(acc2[2][0], a23.x, b2.x); FMA2(acc2[2][1], a23.x, b2.y);
        FMA2(acc2[3][0], a23.y, b2.x); FMA2(acc2[3][1], a23.y, b2.y);
    }
    ulonglong2 bias2 = *(const ulonglong2*)(g_br + n0 + tn);
    #pragma unroll
    for (int i = 0; i < 4; i++) {
        ulonglong2 r;
        ADD2(r.x, acc2[i][0], bias2.x);
        ADD2(r.y, acc2[i][1], bias2.y);
        *(ulonglong2*)(g_Xp + (size_t)(m0 + tm + i) * GG + n0 + tn) = r;
    }
}

// ---------------- LSTM recurrence: cluster-resident W, 512 threads ----------------
// smem layout (dynamic):
//   sh_h  : ull [16 b][256 k]      32KB   (dup'd h)
//   red   : ull [16 b][8 kq][64]   64KB   (partial gate-pair sums)
//   xbuf  : float [2][16 b][128]   16KB   (Xp slice double buffer)
#define SH_H_ULL   (NBC*HH)          // 4096
#define RED_ULL    (NBC*8*64)        // 8192
#define XBUF_F     (2*NBC*128)       // 4096
#define LSTM_SMEM  (SH_H_ULL*8 + RED_ULL*8 + XBUF_F*4)   // 114688

__global__ void __launch_bounds__(NT, 1) __cluster_dims__(CL, 1, 1)
lstm_kernel(const float* __restrict__ h0, const float* __restrict__ c0,
            float* __restrict__ out) {
    extern __shared__ __align__(16) char smem[];
    ull*   sh_h = (ull*)smem;                               // [b][k]
    ull*   red  = sh_h + SH_H_ULL;                          // [b][kq][rrp]
    float* xbuf = (float*)(red + RED_ULL);                  // [buf][b][128]

    const int tid   = threadIdx.x;
    const int slice = blockIdx.x & (CL - 1);
    const int cl    = blockIdx.x >> 3;
    const int b0c   = cl * NBC;

    // mainloop mapping
    const int kq    = tid >> 6;                // 0..7, 32 k each
    const int rrp   = tid & 63;                // rr-pair within slice
    const int kbase = kq * 32;
    const int rrbase = slice * 128 + 2 * rrp;

    // epilogue mapping
    const int jl = tid & 31;                   // local j 0..31
    const int eb = tid >> 5;                   // batch 0..15

    // ---- prologue ----
    ull wreg[32];
    #pragma unroll
    for (int kk = 0; kk < 32; kk++)
        wreg[kk] = *(const ull*)(g_Wt + (size_t)(kbase + kk) * GG + rrbase);

    for (int i = tid; i < NBC * HH; i += NT) {
        int b = i >> 8, k = i & 255;
        sh_h[b * HH + k] = dupf(h0[(size_t)(b0c + b) * HH + k]);
    }
    float creg = c0[(size_t)(b0c + eb) * HH + slice * 32 + jl];
    float hlast = 0.f;

    // prefetch Xp slice for t=0 into xbuf[0]: 8KB, one CP16 per thread
    {
        int b = tid >> 5, q = tid & 31;
        unsigned dst = (unsigned)__cvta_generic_to_shared(xbuf + b * 128 + q * 4);
        const float* src = g_Xp + ((size_t)(b0c + b) * TT + 0) * GG + slice * 128 + q * 4;
        CP16(dst, src);
        CP_COMMIT();
    }
    __syncthreads();

    // ---- time loop ----
    for (int t = 0; t < TT; t++) {
        CP_WAIT(1);             // h-fill (prev step) done
        __syncthreads();

        ull acc[NBC];
        #pragma unroll
        for (int b = 0; b < NBC; b++) acc[b] = 0ull;

        #pragma unroll
        for (int kk = 0; kk < 32; kk += 2) {
            #pragma unroll
            for (int b = 0; b < NBC; b++) {
                ulonglong2 h2 = *(const ulonglong2*)(sh_h + b * HH + kbase + kk);
                FMA2(acc[b], wreg[kk],     h2.x);
                FMA2(acc[b], wreg[kk + 1], h2.y);
            }
        }

        #pragma unroll
        for (int b = 0; b < NBC; b++)
            red[(b * 8 + kq) * 64 + rrp] = acc[b];

        CP_WAIT(0);             // x(t) ready
        __syncthreads();        // red + xbuf visible

        // epilogue: thread owns (j = slice*32+jl, batch eb)
        {
            const ull* rp = red + (eb * 8) * 64 + 2 * jl;
            ulonglong2 s0 = *(const ulonglong2*)(rp);
            ulonglong2 s1 = *(const ulonglong2*)(rp + 64);
            ulonglong2 s2 = *(const ulonglong2*)(rp + 128);
            ulonglong2 s3 = *(const ulonglong2*)(rp + 192);
            ulonglong2 s4 = *(const ulonglong2*)(rp + 256);
            ulonglong2 s5 = *(const ulonglong2*)(rp + 320);
            ulonglong2 s6 = *(const ulonglong2*)(rp + 384);
            ulonglong2 s7 = *(const ulonglong2*)(rp + 448);
            ull a0, a1, a2, a3, sif, sgo;
            ADD2(a0, s0.x, s1.x); ADD2(a1, s2.x, s3.x);
            ADD2(a2, s4.x, s5.x); ADD2(a3, s6.x, s7.x);
            ADD2(a0, a0, a1); ADD2(a2, a2, a3); ADD2(sif, a0, a2);
            ADD2(a0, s0.y, s1.y); ADD2(a1, s2.y, s3.y);
            ADD2(a2, s4.y, s5.y); ADD2(a3, s6.y, s7.y);
            ADD2(a0, a0, a1); ADD2(a2, a2, a3); ADD2(sgo, a0, a2);

            float4 xv = *(const float4*)(xbuf + ((size_t)(t & 1) * NBC + eb) * 128 + 4 * jl);
            float ig = sigf(xv.x + lof(sif));
            float fg = sigf(xv.y + hif(sif));
            float gg = thf (xv.z + lof(sgo));
            float og = sigf(xv.w + hif(sgo));
            creg  = fg * creg + ig * gg;
            hlast = og * thf(creg);
            // publish dup'd h, coalesced: g_hex[cl][b][k]
            g_hex[((size_t)cl * NBC + eb) * HH + slice * 32 + jl] = dupf(hlast);
        }

        if (t < TT - 1) {
            CLUSTER_SYNC();     // arrive=release, wait=acquire: orders g_hex STGs
            // h-fill: 32KB contiguous, 64B per thread
            {
                unsigned dst = (unsigned)__cvta_generic_to_shared((char*)sh_h + tid * 64);
                const char* src = (const char*)(g_hex + (size_t)cl * NBC * HH) + tid * 64;
                CP16(dst, src); CP16(dst + 16, src + 16);
                CP16(dst + 32, src + 32); CP16(dst + 48, src + 48);
                CP_COMMIT();
            }
            // x prefetch for t+1
            {
                int b = tid >> 5, q = tid & 31;
                unsigned dst = (unsigned)__cvta_generic_to_shared(
                    xbuf + ((size_t)((t + 1) & 1) * NBC + b) * 128 + q * 4);
                const float* src = g_Xp + ((size_t)(b0c + b) * TT + (t + 1)) * GG
                                   + slice * 128 + q * 4;
                CP16(dst, src);
                CP_COMMIT();
            }
        }
    }

    // ---- outputs: rnn_outputs @0, logits @65536, h @67584, c @133120 ----
    {
        size_t idx = (size_t)(b0c + eb) * HH + slice * 32 + jl;
        out[idx]          = hlast;
        out[67584 + idx]  = hlast;
        out[133120 + idx] = creg;
    }
}

// ---------------- output projection ----------------
__global__ void logits_kernel(const float* __restrict__ hbase,
                              const float* __restrict__ W_out,
                              const float* __restrict__ b_out,
                              float* __restrict__ out_logits) {
    int b = blockIdx.x;
    int d = threadIdx.x >> 5;
    int lane = threadIdx.x & 31;
    const float* hr = hbase + (size_t)b * HH;
    const float* wr = W_out + (size_t)d * HH;
    float s = 0.f;
    #pragma unroll
    for (int k = lane; k < HH; k += 32) s += hr[k] * wr[k];
    #pragma unroll
    for (int o = 16; o; o >>= 1) s += __shfl_down_sync(0xffffffffu, s, o);
    if (lane == 0) out_logits[b * DOUT + d] = s + b_out[d];
}

// ---------------- launch ----------------
extern "C" void kernel_launch(void* const* d_in, const int* in_sizes, int n_in,
                              void* d_out, int out_size) {
    const float* x     = (const float*)d_in[0];
    const float* h0    = (const float*)d_in[1];
    const float* c0    = (const float*)d_in[2];
    const float* W_ih  = (const float*)d_in[3];
    const float* W_hh  = (const float*)d_in[4];
    const float* bias  = (const float*)d_in[5];
    const float* W_out = (const float*)d_in[6];
    const float* b_out = (const float*)d_in[7];
    float* out = (float*)d_out;

    reorder_whh_kernel<<<HH, 256>>>(W_hh);
    reorder_wih_kernel<<<GG, 64>>>(W_ih, bias);

    xproj_kernel<<<dim3((BB_ * TT) / 64, GG / 64), 256>>>(x);

    static int cfg_done = 0;
    if (!cfg_done) {
        cudaFuncSetAttribute(lstm_kernel, cudaFuncAttributeMaxDynamicSharedMemorySize,
                             LSTM_SMEM);
        cfg_done = 1;
    }
    lstm_kernel<<<NCTA, NT, LSTM_SMEM>>>(h0, c0, out);

    logits_kernel<<<BB_, 256>>>(out, W_out, b_out, out + 65536);
}

// round 7
// speedup vs baseline: 1.2116x; 1.0508x over previous
#include <cuda_runtime.h>
#include <cstdint>

typedef unsigned long long ull;

#define TT 512
#define BB_ 256
#define DIN 64
#define HH 256
#define GG 1024   // 4*H
#define DOUT 8

#define CL 8            // CTAs per cluster
#define NCLUST 16       // clusters
#define NBC 16          // batches per cluster
#define NCTA (NCLUST*CL)
#define NT 512          // threads per lstm CTA

// ---------------- device scratch (static, allowed) ----------------
__device__ __align__(128) float g_Xp[(size_t)BB_*TT*GG];   // [b][t][rr]
__device__ __align__(128) float g_Wt[(size_t)HH*GG];       // [k][rr] reordered W_hh
__device__ __align__(128) float g_Wr_ih[(size_t)GG*DIN];
__device__ __align__(128) float g_br[GG];
__device__ __align__(128) ull   g_hex[(size_t)NCLUST*NBC*HH]; // [cl][b][k] dup'd h

// ---------------- helpers ----------------
__device__ __forceinline__ ull dupf(float f){ unsigned u=__float_as_uint(f); return (ull)u | ((ull)u<<32); }
__device__ __forceinline__ float lof(ull v){ return __uint_as_float((unsigned)v); }
__device__ __forceinline__ float hif(ull v){ return __uint_as_float((unsigned)(v>>32)); }
#define FMA2(acc,a,b) asm("fma.rn.f32x2 %0, %1, %2, %0;" : "+l"(acc) : "l"(a), "l"(b))
#define ADD2(d,a,b)   asm("add.rn.f32x2 %0, %1, %2;" : "=l"(d) : "l"(a), "l"(b))
#define TANHA(d,x)    asm("tanh.approx.f32 %0, %1;" : "=f"(d) : "f"(x))

#define CP16(dst_s, src_g) \
    asm volatile("cp.async.cg.shared.global [%0], [%1], 16;" :: "r"(dst_s), "l"(src_g) : "memory")
#define CP_COMMIT()  asm volatile("cp.async.commit_group;" ::: "memory")
#define CP_WAIT(n)   asm volatile("cp.async.wait_group %0;" :: "n"(n) : "memory")
#define CLUSTER_ARRIVE() asm volatile("barrier.cluster.arrive.aligned;" ::: "memory")
#define CLUSTER_WAIT()   asm volatile("barrier.cluster.wait.aligned;"   ::: "memory")
#define CLUSTER_SYNC() do { CLUSTER_ARRIVE(); CLUSTER_WAIT(); } while(0)

__device__ __forceinline__ void mbar_init(unsigned a, unsigned cnt){
    asm volatile("mbarrier.init.shared.b64 [%0], %1;" :: "r"(a), "r"(cnt) : "memory");
}
__device__ __forceinline__ void mbar_expect(unsigned a, unsigned tx){
    asm volatile("mbarrier.arrive.expect_tx.shared.b64 _, [%0], %1;" :: "r"(a), "r"(tx) : "memory");
}
__device__ __forceinline__ void mbar_wait_par(unsigned a, unsigned ph){
    asm volatile(
        "{\n\t.reg .pred P;\n"
        "W1_%=:\n\t"
        "mbarrier.try_wait.parity.acquire.cta.shared::cta.b64 P, [%0], %1, 0x989680;\n\t"
        "@P bra W2_%=;\n\t"
        "bra W1_%=;\n"
        "W2_%=:\n\t}"
        :: "r"(a), "r"(ph) : "memory");
}
#define BULK_MCAST(dst,src,bytes,mbar,mask) \
    asm volatile("cp.async.bulk.shared::cluster.global.mbarrier::complete_tx::bytes.multicast::cluster " \
                 "[%0], [%1], %2, [%3], %4;" \
                 :: "r"(dst), "l"(src), "r"(bytes), "r"(mbar), "h"((unsigned short)(mask)) : "memory")

// ---------------- weight reorder (one-time) ----------------
// rr = 4*j + g  (g in order i,f,g,o), orig row = g*H + j
__global__ void reorder_whh_kernel(const float* __restrict__ W_hh) {
    int k = blockIdx.x;
    for (int rr = threadIdx.x; rr < GG; rr += blockDim.x) {
        int jj = rr >> 2, g = rr & 3;
        g_Wt[(size_t)k * GG + rr] = W_hh[(size_t)(g * HH + jj) * HH + k];
    }
}

__global__ void reorder_wih_kernel(const float* __restrict__ W_ih,
                                   const float* __restrict__ bias) {
    int rr = blockIdx.x;
    int jj = rr >> 2, g = rr & 3;
    int orig = g * HH + jj;
    if (threadIdx.x < DIN)
        g_Wr_ih[(size_t)rr * DIN + threadIdx.x] = W_ih[(size_t)orig * DIN + threadIdx.x];
    if (threadIdx.x == 0) g_br[rr] = bias[orig];
}

// ---------------- input projection GEMM (f32x2, 64m x 128n tile) ----------------
#define XP_SMEM (DIN*66*8 + DIN*132*4)   // As2 + Bs = 67584
__global__ void __launch_bounds__(256) xproj_kernel(const float* __restrict__ x) {
    extern __shared__ __align__(16) char xsm[];
    ull*   As2 = (ull*)xsm;                 // [k][66] dup'd x
    float* Bs  = (float*)(As2 + DIN * 66);  // [k][132]
    int m0 = blockIdx.x * 64, n0 = blockIdx.y * 128;
    int tid = threadIdx.x;

    for (int i = tid; i < 1024; i += 256) {
        int r  = i >> 4;       // m row 0..63
        int kq = i & 15;
        float4 v = ((const float4*)(x + (size_t)(m0 + r) * DIN))[kq];
        As2[(kq*4+0)*66 + r] = dupf(v.x); As2[(kq*4+1)*66 + r] = dupf(v.y);
        As2[(kq*4+2)*66 + r] = dupf(v.z); As2[(kq*4+3)*66 + r] = dupf(v.w);
    }
    for (int i = tid; i < 2048; i += 256) {
        int r  = i >> 4;       // n row 0..127
        int kq = i & 15;
        float4 w = ((const float4*)(g_Wr_ih + (size_t)(n0 + r) * DIN))[kq];
        Bs[(kq*4+0)*132 + r] = w.x; Bs[(kq*4+1)*132 + r] = w.y;
        Bs[(kq*4+2)*132 + r] = w.z; Bs[(kq*4+3)*132 + r] = w.w;
    }
    __syncthreads();

    int tm = (tid >> 4) << 2;     // 4 m rows
    int tn = (tid & 15) << 3;     // 8 n cols (4 f32x2 pairs)
    ull acc[4][4] = {};
    #pragma unroll 8
    for (int k = 0; k < DIN; k++) {
        ulonglong2 a01 = *(const ulonglong2*)&As2[k*66 + tm];
        ulonglong2 a23 = *(const ulonglong2*)&As2[k*66 + tm + 2];
        ulonglong2 b01 = *(const ulonglong2*)&Bs[k*132 + tn];
        ulonglong2 b23 = *(const ulonglong2*)&Bs[k*132 + tn + 4];
        ull am[4] = {a01.x, a01.y, a23.x, a23.y};
        #pragma unroll
        for (int i = 0; i < 4; i++) {
            FMA2(acc[i][0], am[i], b01.x); FMA2(acc[i][1], am[i], b01.y);
            FMA2(acc[i][2], am[i], b23.x); FMA2(acc[i][3], am[i], b23.y);
        }
    }
    ulonglong2 bias01 = *(const ulonglong2*)(g_br + n0 + tn);
    ulonglong2 bias23 = *(const ulonglong2*)(g_br + n0 + tn + 4);
    #pragma unroll
    for (int i = 0; i < 4; i++) {
        ulonglong2 r0, r1;
        ADD2(r0.x, acc[i][0], bias01.x); ADD2(r0.y, acc[i][1], bias01.y);
        ADD2(r1.x, acc[i][2], bias23.x); ADD2(r1.y, acc[i][3], bias23.y);
        float* orow = g_Xp + (size_t)(m0 + tm + i) * GG + n0 + tn;
        *(ulonglong2*)orow       = r0;
        *(ulonglong2*)(orow + 4) = r1;
    }
}

// ---------------- LSTM recurrence: cluster-resident W, 512 threads ----------------
// smem: sh_h [16b][256k] ull 32KB | red [16b][8kq][64] ull 64KB | xbuf [2][16b][128] f 16KB | mbar
#define SH_H_ULL   (NBC*HH)          // 4096
#define RED_ULL    (NBC*8*64)        // 8192
#define XBUF_F     (2*NBC*128)       // 4096
#define MBAR_OFF   (SH_H_ULL*8 + RED_ULL*8 + XBUF_F*4)   // 114688
#define LSTM_SMEM  (MBAR_OFF + 16)

__global__ void __launch_bounds__(NT, 1) __cluster_dims__(CL, 1, 1)
lstm_kernel(const float* __restrict__ h0, const float* __restrict__ c0,
            float* __restrict__ out) {
    extern __shared__ __align__(16) char smem[];
    ull*   sh_h = (ull*)smem;                               // [b][k]
    ull*   red  = sh_h + SH_H_ULL;                          // [b][kq][rrp]
    float* xbuf = (float*)(red + RED_ULL);                  // [buf][b][128]
    const unsigned sh_h_u32 = (unsigned)__cvta_generic_to_shared(sh_h);
    const unsigned mbar_u32 = (unsigned)__cvta_generic_to_shared(smem + MBAR_OFF);

    const int tid   = threadIdx.x;
    const int slice = blockIdx.x & (CL - 1);
    const int cl    = blockIdx.x >> 3;
    const int b0c   = cl * NBC;

    // mainloop mapping
    const int kq     = tid >> 6;               // 0..7, 32 k each
    const int rrp    = tid & 63;               // rr-pair within slice
    const int kbase  = kq * 32;
    const int rrbase = slice * 128 + 2 * rrp;

    // epilogue mapping
    const int jl = tid & 31;                   // local j 0..31
    const int eb = tid >> 5;                   // batch 0..15

    // ---- prologue ----
    if (tid == 0) mbar_init(mbar_u32, 1);

    ull wreg[32];
    #pragma unroll
    for (int kk = 0; kk < 32; kk++)
        wreg[kk] = *(const ull*)(g_Wt + (size_t)(kbase + kk) * GG + rrbase);

    for (int i = tid; i < NBC * HH; i += NT) {
        int b = i >> 8, k = i & 255;
        sh_h[b * HH + k] = dupf(h0[(size_t)(b0c + b) * HH + k]);
    }
    float creg = c0[(size_t)(b0c + eb) * HH + slice * 32 + jl];
    float hlast = 0.f;

    // prefetch x(0)
    {
        int b = tid >> 5, q = tid & 31;
        unsigned dst = (unsigned)__cvta_generic_to_shared(xbuf + b * 128 + q * 4);
        const float* src = g_Xp + ((size_t)(b0c + b) * TT + 0) * GG + slice * 128 + q * 4;
        CP16(dst, src);
        CP_COMMIT();
    }
    __syncthreads();
    CLUSTER_SYNC();            // all mbarriers initialized cluster-wide

    unsigned ph = 0;

    // ---- time loop ----
    for (int t = 0; t < TT; t++) {
        if (t) { mbar_wait_par(mbar_u32, ph); ph ^= 1; }   // h(t) in sh_h (acquire)

        // mainloop: b-outer, short acc chains -> registers free for load hoisting
        #pragma unroll
        for (int b = 0; b < NBC; b++) {
            const ulonglong2* hp = (const ulonglong2*)(sh_h + b * HH + kbase);
            ull a0 = 0ull, a1 = 0ull;
            #pragma unroll
            for (int kk = 0; kk < 16; kk++) {
                ulonglong2 h2 = hp[kk];
                FMA2(a0, wreg[2*kk],     h2.x);
                FMA2(a1, wreg[2*kk + 1], h2.y);
            }
            ull s; ADD2(s, a0, a1);
            red[(b * 8 + kq) * 64 + rrp] = s;
        }
        __syncthreads();       // red visible

        // epilogue: thread owns (j = slice*32+jl, batch eb)
        {
            const ull* rp = red + (eb * 8) * 64 + 2 * jl;
            ulonglong2 s0 = *(const ulonglong2*)(rp);
            ulonglong2 s1 = *(const ulonglong2*)(rp + 64);
            ulonglong2 s2 = *(const ulonglong2*)(rp + 128);
            ulonglong2 s3 = *(const ulonglong2*)(rp + 192);
            ulonglong2 s4 = *(const ulonglong2*)(rp + 256);
            ulonglong2 s5 = *(const ulonglong2*)(rp + 320);
            ulonglong2 s6 = *(const ulonglong2*)(rp + 384);
            ulonglong2 s7 = *(const ulonglong2*)(rp + 448);
            ull a0, a1, a2, a3, sif, sgo;
            ADD2(a0, s0.x, s1.x); ADD2(a1, s2.x, s3.x);
            ADD2(a2, s4.x, s5.x); ADD2(a3, s6.x, s7.x);
            ADD2(a0, a0, a1); ADD2(a2, a2, a3); ADD2(sif, a0, a2);
            ADD2(a0, s0.y, s1.y); ADD2(a1, s2.y, s3.y);
            ADD2(a2, s4.y, s5.y); ADD2(a3, s6.y, s7.y);
            ADD2(a0, a0, a1); ADD2(a2, a2, a3); ADD2(sgo, a0, a2);

            CP_WAIT(0);        // x(t) ready
            float4 xv = *(const float4*)(xbuf + ((size_t)(t & 1) * NBC + eb) * 128 + 4 * jl);
            float pi = xv.x + lof(sif);
            float pf = xv.y + hif(sif);
            float pg = xv.z + lof(sgo);
            float po = xv.w + hif(sgo);
            float ti, tf_, tg, to, tc;
            TANHA(ti, pi * 0.5f); TANHA(tf_, pf * 0.5f);
            TANHA(tg, pg);        TANHA(to, po * 0.5f);
            float ig = fmaf(ti, 0.5f, 0.5f);
            float fg = fmaf(tf_, 0.5f, 0.5f);
            float og = fmaf(to, 0.5f, 0.5f);
            creg  = fg * creg + ig * tg;
            TANHA(tc, creg);
            hlast = og * tc;
            g_hex[((size_t)cl * NBC + eb) * HH + slice * 32 + jl] = dupf(hlast);
        }

        if (t < TT - 1) {
            if (tid == 0) mbar_expect(mbar_u32, 32768);
            CLUSTER_ARRIVE();                       // release: orders g_hex STGs
            // overlap: x prefetch for t+1 between arrive and wait
            {
                int b = tid >> 5, q = tid & 31;
                unsigned dst = (unsigned)__cvta_generic_to_shared(
                    xbuf + ((size_t)((t + 1) & 1) * NBC + b) * 128 + q * 4);
                const float* src = g_Xp + ((size_t)(b0c + b) * TT + (t + 1)) * GG
                                   + slice * 128 + q * 4;
                CP16(dst, src);
                CP_COMMIT();
            }
            CLUSTER_WAIT();                         // acquire: all slices in g_hex
            if (slice == 0 && tid == 0)             // leader: one 32KB multicast fill
                BULK_MCAST(sh_h_u32, (const void*)(g_hex + (size_t)cl * NBC * HH),
                           32768u, mbar_u32, 0xFFu);
        }
    }

    // ---- outputs: rnn_outputs @0, logits @65536, h @67584, c @133120 ----
    {
        size_t idx = (size_t)(b0c + eb) * HH + slice * 32 + jl;
        out[idx]          = hlast;
        out[67584 + idx]  = hlast;
        out[133120 + idx] = creg;
    }
    CLUSTER_SYNC();
}

// ---------------- output projection ----------------
__global__ void logits_kernel(const float* __restrict__ hbase,
                              const float* __restrict__ W_out,
                              const float* __restrict__ b_out,
                              float* __restrict__ out_logits) {
    int b = blockIdx.x;
    int d = threadIdx.x >> 5;
    int lane = threadIdx.x & 31;
    const float* hr = hbase + (size_t)b * HH;
    const float* wr = W_out + (size_t)d * HH;
    float s = 0.f;
    #pragma unroll
    for (int k = lane; k < HH; k += 32) s += hr[k] * wr[k];
    #pragma unroll
    for (int o = 16; o; o >>= 1) s += __shfl_down_sync(0xffffffffu, s, o);
    if (lane == 0) out_logits[b * DOUT + d] = s + b_out[d];
}

// ---------------- launch ----------------
extern "C" void kernel_launch(void* const* d_in, const int* in_sizes, int n_in,
                              void* d_out, int out_size) {
    const float* x     = (const float*)d_in[0];
    const float* h0    = (const float*)d_in[1];
    const float* c0    = (const float*)d_in[2];
    const float* W_ih  = (const float*)d_in[3];
    const float* W_hh  = (const float*)d_in[4];
    const float* bias  = (const float*)d_in[5];
    const float* W_out = (const float*)d_in[6];
    const float* b_out = (const float*)d_in[7];
    float* out = (float*)d_out;

    static int cfg_done = 0;
    if (!cfg_done) {
        cudaFuncSetAttribute(lstm_kernel, cudaFuncAttributeMaxDynamicSharedMemorySize,
                             LSTM_SMEM);
        cudaFuncSetAttribute(xproj_kernel, cudaFuncAttributeMaxDynamicSharedMemorySize,
                             XP_SMEM);
        cfg_done = 1;
    }

    reorder_whh_kernel<<<HH, 256>>>(W_hh);
    reorder_wih_kernel<<<GG, 64>>>(W_ih, bias);

    xproj_kernel<<<dim3((BB_ * TT) / 64, GG / 128), 256, XP_SMEM>>>(x);

    lstm_kernel<<<NCTA, NT, LSTM_SMEM>>>(h0, c0, out);

    logits_kernel<<<BB_, 256>>>(out, W_out, b_out, out + 65536);
}

// round 8
// speedup vs baseline: 1.4293x; 1.1797x over previous
#include <cuda_runtime.h>
#include <cstdint>

typedef unsigned long long ull;

#define TT 512
#define BB_ 256
#define DIN 64
#define HH 256
#define GG 1024   // 4*H
#define DOUT 8

#define CL 8            // CTAs per cluster
#define NCLUST 16       // clusters
#define NBC 16          // batches per cluster
#define NCTA (NCLUST*CL)
#define NT 512          // threads per lstm CTA

// ---------------- device scratch (static, allowed) ----------------
__device__ __align__(128) float g_Xp[(size_t)BB_*TT*GG];   // [b][t][rr]
__device__ __align__(128) float g_Wt[(size_t)HH*GG];       // [k][rr] reordered W_hh
__device__ __align__(128) float g_Wr_ih[(size_t)GG*DIN];
__device__ __align__(128) float g_br[GG];
__device__ __align__(128) ull   g_hex[(size_t)NCLUST*NBC*HH]; // [cl][b][k] dup'd h

// ---------------- helpers ----------------
__device__ __forceinline__ ull dupf(float f){ unsigned u=__float_as_uint(f); return (ull)u | ((ull)u<<32); }
__device__ __forceinline__ float lof(ull v){ return __uint_as_float((unsigned)v); }
__device__ __forceinline__ float hif(ull v){ return __uint_as_float((unsigned)(v>>32)); }
#define FMA2(acc,a,b) asm("fma.rn.f32x2 %0, %1, %2, %0;" : "+l"(acc) : "l"(a), "l"(b))
#define ADD2(d,a,b)   asm("add.rn.f32x2 %0, %1, %2;" : "=l"(d) : "l"(a), "l"(b))
#define TANHA(d,x)    asm("tanh.approx.f32 %0, %1;" : "=f"(d) : "f"(x))

#define CP16(dst_s, src_g) \
    asm volatile("cp.async.cg.shared.global [%0], [%1], 16;" :: "r"(dst_s), "l"(src_g) : "memory")
#define CP_COMMIT()  asm volatile("cp.async.commit_group;" ::: "memory")
#define CP_WAIT(n)   asm volatile("cp.async.wait_group %0;" :: "n"(n) : "memory")
#define CLUSTER_SYNC() do { \
    asm volatile("barrier.cluster.arrive.aligned;" ::: "memory"); \
    asm volatile("barrier.cluster.wait.aligned;"   ::: "memory"); } while(0)

__device__ __forceinline__ void mbar_init(unsigned a, unsigned cnt){
    asm volatile("mbarrier.init.shared.b64 [%0], %1;" :: "r"(a), "r"(cnt) : "memory");
}
__device__ __forceinline__ void mbar_expect(unsigned a, unsigned tx){
    asm volatile("mbarrier.arrive.expect_tx.shared.b64 _, [%0], %1;" :: "r"(a), "r"(tx) : "memory");
}
__device__ __forceinline__ void mbar_wait_par(unsigned a, unsigned ph){
    asm volatile(
        "{\n\t.reg .pred P;\n"
        "W1_%=:\n\t"
        "mbarrier.try_wait.parity.acquire.cta.shared::cta.b64 P, [%0], %1, 0x989680;\n\t"
        "@P bra W2_%=;\n\t"
        "bra W1_%=;\n"
        "W2_%=:\n\t}"
        :: "r"(a), "r"(ph) : "memory");
}
#define BULK_MCAST(dst,src,bytes,mbar,mask) \
    asm volatile("cp.async.bulk.shared::cluster.global.mbarrier::complete_tx::bytes.multicast::cluster " \
                 "[%0], [%1], %2, [%3], %4;" \
                 :: "r"(dst), "l"(src), "r"(bytes), "r"(mbar), "h"((unsigned short)(mask)) : "memory")
#define FENCE_ASYNC_GLOBAL() asm volatile("fence.proxy.async.global;" ::: "memory")

// ---------------- weight reorder (one-time) ----------------
// rr = 4*j + g  (g in order i,f,g,o), orig row = g*H + j
__global__ void reorder_whh_kernel(const float* __restrict__ W_hh) {
    int k = blockIdx.x;
    for (int rr = threadIdx.x; rr < GG; rr += blockDim.x) {
        int jj = rr >> 2, g = rr & 3;
        g_Wt[(size_t)k * GG + rr] = W_hh[(size_t)(g * HH + jj) * HH + k];
    }
}

__global__ void reorder_wih_kernel(const float* __restrict__ W_ih,
                                   const float* __restrict__ bias) {
    int rr = blockIdx.x;
    int jj = rr >> 2, g = rr & 3;
    int orig = g * HH + jj;
    if (threadIdx.x < DIN)
        g_Wr_ih[(size_t)rr * DIN + threadIdx.x] = W_ih[(size_t)orig * DIN + threadIdx.x];
    if (threadIdx.x == 0) g_br[rr] = bias[orig];
}

// ---------------- input projection GEMM (f32x2, 64m x 128n tile) ----------------
#define XP_SMEM (DIN*66*8 + DIN*132*4)   // As2 + Bs = 67584
__global__ void __launch_bounds__(256) xproj_kernel(const float* __restrict__ x) {
    extern __shared__ __align__(16) char xsm[];
    ull*   As2 = (ull*)xsm;                 // [k][66] dup'd x
    float* Bs  = (float*)(As2 + DIN * 66);  // [k][132]
    int m0 = blockIdx.x * 64, n0 = blockIdx.y * 128;
    int tid = threadIdx.x;

    for (int i = tid; i < 1024; i += 256) {
        int r  = i >> 4;       // m row 0..63
        int kq = i & 15;
        float4 v = ((const float4*)(x + (size_t)(m0 + r) * DIN))[kq];
        As2[(kq*4+0)*66 + r] = dupf(v.x); As2[(kq*4+1)*66 + r] = dupf(v.y);
        As2[(kq*4+2)*66 + r] = dupf(v.z); As2[(kq*4+3)*66 + r] = dupf(v.w);
    }
    for (int i = tid; i < 2048; i += 256) {
        int r  = i >> 4;       // n row 0..127
        int kq = i & 15;
        float4 w = ((const float4*)(g_Wr_ih + (size_t)(n0 + r) * DIN))[kq];
        Bs[(kq*4+0)*132 + r] = w.x; Bs[(kq*4+1)*132 + r] = w.y;
        Bs[(kq*4+2)*132 + r] = w.z; Bs[(kq*4+3)*132 + r] = w.w;
    }
    __syncthreads();

    int tm = (tid >> 4) << 2;     // 4 m rows
    int tn = (tid & 15) << 3;     // 8 n cols (4 f32x2 pairs)
    ull acc[4][4] = {};
    #pragma unroll 8
    for (int k = 0; k < DIN; k++) {
        ulonglong2 a01 = *(const ulonglong2*)&As2[k*66 + tm];
        ulonglong2 a23 = *(const ulonglong2*)&As2[k*66 + tm + 2];
        ulonglong2 b01 = *(const ulonglong2*)&Bs[k*132 + tn];
        ulonglong2 b23 = *(const ulonglong2*)&Bs[k*132 + tn + 4];
        ull am[4] = {a01.x, a01.y, a23.x, a23.y};
        #pragma unroll
        for (int i = 0; i < 4; i++) {
            FMA2(acc[i][0], am[i], b01.x); FMA2(acc[i][1], am[i], b01.y);
            FMA2(acc[i][2], am[i], b23.x); FMA2(acc[i][3], am[i], b23.y);
        }
    }
    ulonglong2 bias01 = *(const ulonglong2*)(g_br + n0 + tn);
    ulonglong2 bias23 = *(const ulonglong2*)(g_br + n0 + tn + 4);
    #pragma unroll
    for (int i = 0; i < 4; i++) {
        ulonglong2 r0, r1;
        ADD2(r0.x, acc[i][0], bias01.x); ADD2(r0.y, acc[i][1], bias01.y);
        ADD2(r1.x, acc[i][2], bias23.x); ADD2(r1.y, acc[i][3], bias23.y);
        float* orow = g_Xp + (size_t)(m0 + tm + i) * GG + n0 + tn;
        *(ulonglong2*)orow       = r0;
        *(ulonglong2*)(orow + 4) = r1;
    }
}

// ---------------- LSTM recurrence ----------------
// smem: shbuf[2][16b][256k] ull 64KB | red [16b][16kq][64p] ull 128KB |
//       xbuf [2][16b][128] f 16KB | mbar[2]
#define SHBUF_ULL  (NBC*HH)                 // 4096 per buffer
#define RED_ULL    (NBC*16*64)              // 16384
#define XBUF_F     (2*NBC*128)              // 4096
#define MBAR_OFF   (2*SHBUF_ULL*8 + RED_ULL*8 + XBUF_F*4)   // 212992
#define LSTM_SMEM  (MBAR_OFF + 32)

__global__ void __launch_bounds__(NT, 1) __cluster_dims__(CL, 1, 1)
lstm_kernel(const float* __restrict__ h0, const float* __restrict__ c0,
            float* __restrict__ out) {
    extern __shared__ __align__(16) char smem[];
    ull*   sh0  = (ull*)smem;                               // buffer 0 [b][k]
    ull*   sh1  = sh0 + SHBUF_ULL;                          // buffer 1
    ull*   red  = sh1 + SHBUF_ULL;                          // [b][kq][pair]
    float* xbuf = (float*)(red + RED_ULL);                  // [buf][b][128]
    const unsigned sh0_u32  = (unsigned)__cvta_generic_to_shared(sh0);
    const unsigned mbar0    = (unsigned)__cvta_generic_to_shared(smem + MBAR_OFF);
    const unsigned mbar1    = mbar0 + 8;

    const int tid   = threadIdx.x;
    const int slice = blockIdx.x & (CL - 1);
    const int cl    = blockIdx.x >> 3;
    const int b0c   = cl * NBC;

    // mainloop mapping: kq warp-uniform (broadcast LDS), 2 gate-pairs/thread
    const int kq    = tid >> 5;                // 0..15, 16 k each
    const int pg    = tid & 31;                // pair group: pairs 2pg, 2pg+1
    const int kbase = kq * 16;

    // epilogue mapping
    const int jl = tid & 31;                   // local j 0..31
    const int eb = tid >> 5;                   // batch 0..15

    // ---- prologue ----
    if (tid == 0) { mbar_init(mbar0, 1); mbar_init(mbar1, 1); }

    // resident weights: wreg[2*kk+p] = W[kbase+kk][slice*128 + 4*pg + 2p .. +1]
    ull wreg[32];
    #pragma unroll
    for (int kk = 0; kk < 16; kk++) {
        ulonglong2 w2 = *(const ulonglong2*)(g_Wt + (size_t)(kbase + kk) * GG
                                             + slice * 128 + 4 * pg);
        wreg[2*kk]     = w2.x;
        wreg[2*kk + 1] = w2.y;
    }

    for (int i = tid; i < NBC * HH; i += NT) {
        int b = i >> 8, k = i & 255;
        sh0[b * HH + k] = dupf(h0[(size_t)(b0c + b) * HH + k]);
    }
    float creg = c0[(size_t)(b0c + eb) * HH + slice * 32 + jl];
    float hlast = 0.f;

    // prefetch x(0)
    {
        int b = tid >> 5, q = tid & 31;
        unsigned dst = (unsigned)__cvta_generic_to_shared(xbuf + b * 128 + q * 4);
        const float* src = g_Xp + ((size_t)(b0c + b) * TT + 0) * GG + slice * 128 + q * 4;
        CP16(dst, src);
        CP_COMMIT();
    }
    __syncthreads();
    CLUSTER_SYNC();            // mbarriers initialized cluster-wide before any mcast

    unsigned ph0 = 0, ph1 = 0;

    // ---- time loop ----
    #pragma unroll 1
    for (int t = 0; t < TT; t++) {
        const ull* shcur = (t & 1) ? sh1 : sh0;
        if (t) {
            if (t & 1) { mbar_wait_par(mbar1, ph1); ph1 ^= 1; }
            else       { mbar_wait_par(mbar0, ph0); ph0 ^= 1; }
        }

        // mainloop: b-outer; per b: 8 broadcast LDS.128, 32 FMA2, 4 chains
        #pragma unroll
        for (int b = 0; b < NBC; b++) {
            const ulonglong2* hp = (const ulonglong2*)(shcur + b * HH + kbase);
            ull a0 = 0ull, a1 = 0ull, a2 = 0ull, a3 = 0ull;
            #pragma unroll
            for (int kk = 0; kk < 16; kk += 2) {
                ulonglong2 h2 = hp[kk >> 1];
                FMA2(a0, wreg[2*kk],     h2.x);
                FMA2(a1, wreg[2*kk + 1], h2.x);
                FMA2(a2, wreg[2*kk + 2], h2.y);
                FMA2(a3, wreg[2*kk + 3], h2.y);
            }
            ulonglong2 s;
            ADD2(s.x, a0, a2);     // pair 2pg   (k-even + k-odd halves)
            ADD2(s.y, a1, a3);     // pair 2pg+1
            *(ulonglong2*)(red + (b * 16 + kq) * 64 + 2 * pg) = s;
        }
        __syncthreads();       // red complete

        // x prefetch for t+1 (overlaps epilogue)
        if (t + 1 < TT) {
            int b = tid >> 5, q = tid & 31;
            unsigned dst = (unsigned)__cvta_generic_to_shared(
                xbuf + ((size_t)((t + 1) & 1) * NBC + b) * 128 + q * 4);
            const float* src = g_Xp + ((size_t)(b0c + b) * TT + (t + 1)) * GG
                               + slice * 128 + q * 4;
            CP16(dst, src);
            CP_COMMIT();
        }

        // epilogue: thread owns (j = slice*32+jl, batch eb)
        {
            const ull* rp = red + (eb * 16) * 64 + 2 * jl;
            ull sx[8], sy[8];
            #pragma unroll
            for (int q = 0; q < 8; q++) {
                ulonglong2 u = *(const ulonglong2*)(rp + (2*q) * 64);
                ulonglong2 v = *(const ulonglong2*)(rp + (2*q + 1) * 64);
                ADD2(sx[q], u.x, v.x);
                ADD2(sy[q], u.y, v.y);
            }
            ull sif, sgo, t0, t1, t2, t3;
            ADD2(t0, sx[0], sx[1]); ADD2(t1, sx[2], sx[3]);
            ADD2(t2, sx[4], sx[5]); ADD2(t3, sx[6], sx[7]);
            ADD2(t0, t0, t1); ADD2(t2, t2, t3); ADD2(sif, t0, t2);
            ADD2(t0, sy[0], sy[1]); ADD2(t1, sy[2], sy[3]);
            ADD2(t2, sy[4], sy[5]); ADD2(t3, sy[6], sy[7]);
            ADD2(t0, t0, t1); ADD2(t2, t2, t3); ADD2(sgo, t0, t2);

            if (t == TT - 1) { CP_WAIT(0); } else { CP_WAIT(1); }   // x(t) ready
            float4 xv = *(const float4*)(xbuf + ((size_t)(t & 1) * NBC + eb) * 128 + 4 * jl);
            float pi = xv.x + lof(sif);
            float pf = xv.y + hif(sif);
            float pgx = xv.z + lof(sgo);
            float po = xv.w + hif(sgo);
            float ti, tf_, tg, to, tc;
            TANHA(ti, pi * 0.5f); TANHA(tf_, pf * 0.5f);
            TANHA(tg, pgx);       TANHA(to, po * 0.5f);
            float ig = fmaf(ti, 0.5f, 0.5f);
            float fg = fmaf(tf_, 0.5f, 0.5f);
            float og = fmaf(to, 0.5f, 0.5f);
            creg  = fg * creg + ig * tg;
            TANHA(tc, creg);
            hlast = og * tc;
            // coalesced: g_hex[cl][b][k]
            g_hex[((size_t)(cl * NBC + eb)) * HH + slice * 32 + jl] = dupf(hlast);
        }
        __syncthreads();       // all STGs done; red free for next mainloop

        if (t + 1 < TT) {
            // each CTA multicasts its own slice (16 x 256B) into everyone's next buffer
            unsigned nb = (t + 1) & 1;
            if (tid == 0) mbar_expect(nb ? mbar1 : mbar0, 32768);
            if (tid < NBC) {
                FENCE_ASYNC_GLOBAL();
                unsigned dst = sh0_u32 + nb * 32768u + (unsigned)(tid * 2048 + slice * 256);
                const void* src = (const void*)(g_hex + ((size_t)(cl * NBC + tid)) * HH
                                                + slice * 32);
                BULK_MCAST(dst, src, 256u, nb ? mbar1 : mbar0, 0xFFu);
            }
        }
    }

    // ---- outputs: rnn_outputs @0, logits @65536, h @67584, c @133120 ----
    {
        size_t idx = (size_t)(b0c + eb) * HH + slice * 32 + jl;
        out[idx]          = hlast;
        out[67584 + idx]  = hlast;
        out[133120 + idx] = creg;
    }
    CLUSTER_SYNC();
}

// ---------------- output projection ----------------
__global__ void logits_kernel(const float* __restrict__ hbase,
                              const float* __restrict__ W_out,
                              const float* __restrict__ b_out,
                              float* __restrict__ out_logits) {
    int b = blockIdx.x;
    int d = threadIdx.x >> 5;
    int lane = threadIdx.x & 31;
    const float* hr = hbase + (size_t)b * HH;
    const float* wr = W_out + (size_t)d * HH;
    float s = 0.f;
    #pragma unroll
    for (int k = lane; k < HH; k += 32) s += hr[k] * wr[k];
    #pragma unroll
    for (int o = 16; o; o >>= 1) s += __shfl_down_sync(0xffffffffu, s, o);
    if (lane == 0) out_logits[b * DOUT + d] = s + b_out[d];
}

// ---------------- launch ----------------
extern "C" void kernel_launch(void* const* d_in, const int* in_sizes, int n_in,
                              void* d_out, int out_size) {
    const float* x     = (const float*)d_in[0];
    const float* h0    = (const float*)d_in[1];
    const float* c0    = (const float*)d_in[2];
    const float* W_ih  = (const float*)d_in[3];
    const float* W_hh  = (const float*)d_in[4];
    const float* bias  = (const float*)d_in[5];
    const float* W_out = (const float*)d_in[6];
    const float* b_out = (const float*)d_in[7];
    float* out = (float*)d_out;

    static int cfg_done = 0;
    if (!cfg_done) {
        cudaFuncSetAttribute(lstm_kernel, cudaFuncAttributeMaxDynamicSharedMemorySize,
                             LSTM_SMEM);
        cudaFuncSetAttribute(xproj_kernel, cudaFuncAttributeMaxDynamicSharedMemorySize,
                             XP_SMEM);
        cfg_done = 1;
    }

    reorder_whh_kernel<<<HH, 256>>>(W_hh);
    reorder_wih_kernel<<<GG, 64>>>(W_ih, bias);

    xproj_kernel<<<dim3((BB_ * TT) / 64, GG / 128), 256, XP_SMEM>>>(x);

    lstm_kernel<<<NCTA, NT, LSTM_SMEM>>>(h0, c0, out);

    logits_kernel<<<BB_, 256>>>(out, W_out, b_out, out + 65536);
}

// round 9
// speedup vs baseline: 1.4762x; 1.0328x over previous
#include <cuda_runtime.h>
#include <cstdint>

typedef unsigned long long ull;

#define TT 512
#define BB_ 256
#define DIN 64
#define HH 256
#define GG 1024   // 4*H
#define DOUT 8

#define CL 8            // CTAs per cluster
#define NCLUST 16       // clusters
#define NBC 16          // batches per cluster
#define NCTA (NCLUST*CL)
#define NT 512          // threads per lstm CTA

// ---------------- device scratch (static, allowed) ----------------
__device__ __align__(128) float g_Xp[(size_t)BB_*TT*GG];   // [b][t][rr]
__device__ __align__(128) float g_Wt[(size_t)HH*GG];       // [k][rr] reordered W_hh
__device__ __align__(128) float g_Wr_ih[(size_t)GG*DIN];
__device__ __align__(128) float g_br[GG];

// ---------------- helpers ----------------
__device__ __forceinline__ ull dupf(float f){ unsigned u=__float_as_uint(f); return (ull)u | ((ull)u<<32); }
__device__ __forceinline__ float lof(ull v){ return __uint_as_float((unsigned)v); }
__device__ __forceinline__ float hif(ull v){ return __uint_as_float((unsigned)(v>>32)); }
#define FMA2(acc,a,b) asm("fma.rn.f32x2 %0, %1, %2, %0;" : "+l"(acc) : "l"(a), "l"(b))
#define ADD2(d,a,b)   asm("add.rn.f32x2 %0, %1, %2;" : "=l"(d) : "l"(a), "l"(b))
#define TANHA(d,x)    asm("tanh.approx.f32 %0, %1;" : "=f"(d) : "f"(x))

#define CP16(dst_s, src_g) \
    asm volatile("cp.async.cg.shared.global [%0], [%1], 16;" :: "r"(dst_s), "l"(src_g) : "memory")
#define CP_COMMIT()  asm volatile("cp.async.commit_group;" ::: "memory")
#define CP_WAIT(n)   asm volatile("cp.async.wait_group %0;" :: "n"(n) : "memory")
#define CLUSTER_SYNC() do { \
    asm volatile("barrier.cluster.arrive.aligned;" ::: "memory"); \
    asm volatile("barrier.cluster.wait.aligned;"   ::: "memory"); } while(0)

__device__ __forceinline__ void mbar_init(unsigned a, unsigned cnt){
    asm volatile("mbarrier.init.shared.b64 [%0], %1;" :: "r"(a), "r"(cnt) : "memory");
}
__device__ __forceinline__ void mbar_expect(unsigned a, unsigned tx){
    asm volatile("mbarrier.arrive.expect_tx.shared.b64 _, [%0], %1;" :: "r"(a), "r"(tx) : "memory");
}
__device__ __forceinline__ void mbar_wait_par(unsigned a, unsigned ph){
    asm volatile(
        "{\n\t.reg .pred P;\n"
        "W1_%=:\n\t"
        "mbarrier.try_wait.parity.acquire.cta.shared::cta.b64 P, [%0], %1, 0x989680;\n\t"
        "@P bra W2_%=;\n\t"
        "bra W1_%=;\n"
        "W2_%=:\n\t}"
        :: "r"(a), "r"(ph) : "memory");
}
__device__ __forceinline__ unsigned mapa_sh(unsigned addr, unsigned rank){
    unsigned r;
    asm("mapa.shared::cluster.u32 %0, %1, %2;" : "=r"(r) : "r"(addr), "r"(rank));
    return r;
}
__device__ __forceinline__ void st_async8(unsigned raddr, ull v, unsigned rmbar){
    asm volatile("st.async.weak.shared::cluster.mbarrier::complete_tx::bytes.b64 [%0], %1, [%2];"
                 :: "r"(raddr), "l"(v), "r"(rmbar) : "memory");
}

// ---------------- weight reorder (one-time) ----------------
// rr = 4*j + g  (g in order i,f,g,o), orig row = g*H + j
__global__ void reorder_whh_kernel(const float* __restrict__ W_hh) {
    int k = blockIdx.x;
    for (int rr = threadIdx.x; rr < GG; rr += blockDim.x) {
        int jj = rr >> 2, g = rr & 3;
        g_Wt[(size_t)k * GG + rr] = W_hh[(size_t)(g * HH + jj) * HH + k];
    }
}

__global__ void reorder_wih_kernel(const float* __restrict__ W_ih,
                                   const float* __restrict__ bias) {
    int rr = blockIdx.x;
    int jj = rr >> 2, g = rr & 3;
    int orig = g * HH + jj;
    if (threadIdx.x < DIN)
        g_Wr_ih[(size_t)rr * DIN + threadIdx.x] = W_ih[(size_t)orig * DIN + threadIdx.x];
    if (threadIdx.x == 0) g_br[rr] = bias[orig];
}

// ---------------- input projection GEMM (f32x2, 64m x 128n tile) ----------------
#define XP_SMEM (DIN*66*8 + DIN*132*4)   // As2 + Bs = 67584
__global__ void __launch_bounds__(256) xproj_kernel(const float* __restrict__ x) {
    extern __shared__ __align__(16) char xsm[];
    ull*   As2 = (ull*)xsm;                 // [k][66] dup'd x
    float* Bs  = (float*)(As2 + DIN * 66);  // [k][132]
    int m0 = blockIdx.x * 64, n0 = blockIdx.y * 128;
    int tid = threadIdx.x;

    for (int i = tid; i < 1024; i += 256) {
        int r  = i >> 4;       // m row 0..63
        int kq = i & 15;
        float4 v = ((const float4*)(x + (size_t)(m0 + r) * DIN))[kq];
        As2[(kq*4+0)*66 + r] = dupf(v.x); As2[(kq*4+1)*66 + r] = dupf(v.y);
        As2[(kq*4+2)*66 + r] = dupf(v.z); As2[(kq*4+3)*66 + r] = dupf(v.w);
    }
    for (int i = tid; i < 2048; i += 256) {
        int r  = i >> 4;       // n row 0..127
        int kq = i & 15;
        float4 w = ((const float4*)(g_Wr_ih + (size_t)(n0 + r) * DIN))[kq];
        Bs[(kq*4+0)*132 + r] = w.x; Bs[(kq*4+1)*132 + r] = w.y;
        Bs[(kq*4+2)*132 + r] = w.z; Bs[(kq*4+3)*132 + r] = w.w;
    }
    __syncthreads();

    int tm = (tid >> 4) << 2;     // 4 m rows
    int tn = (tid & 15) << 3;     // 8 n cols (4 f32x2 pairs)
    ull acc[4][4] = {};
    #pragma unroll 8
    for (int k = 0; k < DIN; k++) {
        ulonglong2 a01 = *(const ulonglong2*)&As2[k*66 + tm];
        ulonglong2 a23 = *(const ulonglong2*)&As2[k*66 + tm + 2];
        ulonglong2 b01 = *(const ulonglong2*)&Bs[k*132 + tn];
        ulonglong2 b23 = *(const ulonglong2*)&Bs[k*132 + tn + 4];
        ull am[4] = {a01.x, a01.y, a23.x, a23.y};
        #pragma unroll
        for (int i = 0; i < 4; i++) {
            FMA2(acc[i][0], am[i], b01.x); FMA2(acc[i][1], am[i], b01.y);
            FMA2(acc[i][2], am[i], b23.x); FMA2(acc[i][3], am[i], b23.y);
        }
    }
    ulonglong2 bias01 = *(const ulonglong2*)(g_br + n0 + tn);
    ulonglong2 bias23 = *(const ulonglong2*)(g_br + n0 + tn + 4);
    #pragma unroll
    for (int i = 0; i < 4; i++) {
        ulonglong2 r0, r1;
        ADD2(r0.x, acc[i][0], bias01.x); ADD2(r0.y, acc[i][1], bias01.y);
        ADD2(r1.x, acc[i][2], bias23.x); ADD2(r1.y, acc[i][3], bias23.y);
        float* orow = g_Xp + (size_t)(m0 + tm + i) * GG + n0 + tn;
        *(ulonglong2*)orow       = r0;
        *(ulonglong2*)(orow + 4) = r1;
    }
}

// ---------------- LSTM recurrence ----------------
// smem: shbuf[2][16b][256k] ull 64KB | red [16b][16kq][64p] ull 128KB |
//       xbuf [2][16b][128] f 16KB | mbar[2]
#define SHBUF_ULL  (NBC*HH)                 // 4096 per buffer
#define RED_ULL    (NBC*16*64)              // 16384
#define XBUF_F     (2*NBC*128)              // 4096
#define MBAR_OFF   (2*SHBUF_ULL*8 + RED_ULL*8 + XBUF_F*4)   // 212992
#define LSTM_SMEM  (MBAR_OFF + 32)

__global__ void __launch_bounds__(NT, 1) __cluster_dims__(CL, 1, 1)
lstm_kernel(const float* __restrict__ h0, const float* __restrict__ c0,
            float* __restrict__ out) {
    extern __shared__ __align__(16) char smem[];
    ull*   sh0  = (ull*)smem;                               // buffer 0 [b][k]
    ull*   sh1  = sh0 + SHBUF_ULL;                          // buffer 1
    ull*   red  = sh1 + SHBUF_ULL;                          // [b][kq][pair]
    float* xbuf = (float*)(red + RED_ULL);                  // [buf][b][128]
    const unsigned sh0_u32  = (unsigned)__cvta_generic_to_shared(sh0);
    const unsigned mbar0    = (unsigned)__cvta_generic_to_shared(smem + MBAR_OFF);
    const unsigned mbar1    = mbar0 + 8;

    const int tid   = threadIdx.x;
    const int slice = blockIdx.x & (CL - 1);
    const int cl    = blockIdx.x >> 3;
    const int b0c   = cl * NBC;

    // mainloop mapping: kq warp-uniform (broadcast LDS), 2 gate-pairs/thread
    const int kq    = tid >> 5;                // 0..15, 16 k each
    const int pg    = tid & 31;                // pair group: pairs 2pg, 2pg+1
    const int kbase = kq * 16;

    // epilogue mapping
    const int jl = tid & 31;                   // local j 0..31
    const int eb = tid >> 5;                   // batch 0..15

    // ---- prologue ----
    if (tid == 0) { mbar_init(mbar0, 1); mbar_init(mbar1, 1); }

    // resident weights: wreg[2*kk+p] = W[kbase+kk][slice*128 + 4*pg + 2p .. +1]
    ull wreg[32];
    #pragma unroll
    for (int kk = 0; kk < 16; kk++) {
        ulonglong2 w2 = *(const ulonglong2*)(g_Wt + (size_t)(kbase + kk) * GG
                                             + slice * 128 + 4 * pg);
        wreg[2*kk]     = w2.x;
        wreg[2*kk + 1] = w2.y;
    }

    for (int i = tid; i < NBC * HH; i += NT) {
        int b = i >> 8, k = i & 255;
        sh0[b * HH + k] = dupf(h0[(size_t)(b0c + b) * HH + k]);
    }
    float creg = c0[(size_t)(b0c + eb) * HH + slice * 32 + jl];
    float hlast = 0.f;

    // this thread's h destination offset within a buffer (bytes): (eb*256 + slice*32 + jl)*8
    const unsigned hdst_off = (unsigned)((eb * HH + slice * 32 + jl) * 8);

    // prefetch x(0)
    {
        int b = tid >> 5, q = tid & 31;
        unsigned dst = (unsigned)__cvta_generic_to_shared(xbuf + b * 128 + q * 4);
        const float* src = g_Xp + ((size_t)(b0c + b) * TT + 0) * GG + slice * 128 + q * 4;
        CP16(dst, src);
        CP_COMMIT();
    }
    __syncthreads();
    CLUSTER_SYNC();            // mbarriers initialized cluster-wide before any st.async

    unsigned ph0 = 0, ph1 = 0;

    // ---- time loop ----
    #pragma unroll 1
    for (int t = 0; t < TT; t++) {
        const ull* shcur = (t & 1) ? sh1 : sh0;
        if (t) {
            if (t & 1) { mbar_wait_par(mbar1, ph1); ph1 ^= 1; }
            else       { mbar_wait_par(mbar0, ph0); ph0 ^= 1; }
        }

        // mainloop: b-outer; per b: 8 broadcast LDS.128, 32 FMA2, 4 chains
        #pragma unroll
        for (int b = 0; b < NBC; b++) {
            const ulonglong2* hp = (const ulonglong2*)(shcur + b * HH + kbase);
            ull a0 = 0ull, a1 = 0ull, a2 = 0ull, a3 = 0ull;
            #pragma unroll
            for (int kk = 0; kk < 16; kk += 2) {
                ulonglong2 h2 = hp[kk >> 1];
                FMA2(a0, wreg[2*kk],     h2.x);
                FMA2(a1, wreg[2*kk + 1], h2.x);
                FMA2(a2, wreg[2*kk + 2], h2.y);
                FMA2(a3, wreg[2*kk + 3], h2.y);
            }
            ulonglong2 s;
            ADD2(s.x, a0, a2);     // pair 2pg
            ADD2(s.y, a1, a3);     // pair 2pg+1
            *(ulonglong2*)(red + (b * 16 + kq) * 64 + 2 * pg) = s;
        }
        __syncthreads();       // red complete (only barrier in the step)

        // x prefetch for t+1 (overlaps epilogue)
        if (t + 1 < TT) {
            int b = tid >> 5, q = tid & 31;
            unsigned dst = (unsigned)__cvta_generic_to_shared(
                xbuf + ((size_t)((t + 1) & 1) * NBC + b) * 128 + q * 4);
            const float* src = g_Xp + ((size_t)(b0c + b) * TT + (t + 1)) * GG
                               + slice * 128 + q * 4;
            CP16(dst, src);
            CP_COMMIT();
        }

        // epilogue: thread owns (j = slice*32+jl, batch eb)
        {
            const ull* rp = red + (eb * 16) * 64 + 2 * jl;
            ull sx[8], sy[8];
            #pragma unroll
            for (int q = 0; q < 8; q++) {
                ulonglong2 u = *(const ulonglong2*)(rp + (2*q) * 64);
                ulonglong2 v = *(const ulonglong2*)(rp + (2*q + 1) * 64);
                ADD2(sx[q], u.x, v.x);
                ADD2(sy[q], u.y, v.y);
            }
            ull sif, sgo, t0, t1, t2, t3;
            ADD2(t0, sx[0], sx[1]); ADD2(t1, sx[2], sx[3]);
            ADD2(t2, sx[4], sx[5]); ADD2(t3, sx[6], sx[7]);
            ADD2(t0, t0, t1); ADD2(t2, t2, t3); ADD2(sif, t0, t2);
            ADD2(t0, sy[0], sy[1]); ADD2(t1, sy[2], sy[3]);
            ADD2(t2, sy[4], sy[5]); ADD2(t3, sy[6], sy[7]);
            ADD2(t0, t0, t1); ADD2(t2, t2, t3); ADD2(sgo, t0, t2);

            if (t == TT - 1) { CP_WAIT(0); } else { CP_WAIT(1); }   // x(t) ready
            float4 xv = *(const float4*)(xbuf + ((size_t)(t & 1) * NBC + eb) * 128 + 4 * jl);
            float pi = xv.x + lof(sif);
            float pf = xv.y + hif(sif);
            float pgx = xv.z + lof(sgo);
            float po = xv.w + hif(sgo);
            float ti, tf_, tg, to, tc;
            TANHA(ti, pi * 0.5f); TANHA(tf_, pf * 0.5f);
            TANHA(tg, pgx);       TANHA(to, po * 0.5f);
            float ig = fmaf(ti, 0.5f, 0.5f);
            float fg = fmaf(tf_, 0.5f, 0.5f);
            float og = fmaf(to, 0.5f, 0.5f);
            creg  = fg * creg + ig * tg;
            TANHA(tc, creg);
            hlast = og * tc;
        }

        // exchange: DSMEM st.async of this thread's dup'd h into all 8 CTAs' next buffer.
        // mbar completion (32KB tx) is the cluster-wide rendezvous; no barrier, no fence.
        if (t + 1 < TT) {
            unsigned nb = (t + 1) & 1;
            unsigned lmbar = nb ? mbar1 : mbar0;
            if (tid == 0) mbar_expect(lmbar, 32768);
            unsigned laddr = sh0_u32 + nb * (unsigned)(SHBUF_ULL * 8) + hdst_off;
            ull hv = dupf(hlast);
            #pragma unroll
            for (int r = 0; r < CL; r++)
                st_async8(mapa_sh(laddr, r), hv, mapa_sh(lmbar, r));
        }
    }

    // ---- outputs: rnn_outputs @0, logits @65536, h @67584, c @133120 ----
    {
        size_t idx = (size_t)(b0c + eb) * HH + slice * 32 + jl;
        out[idx]          = hlast;
        out[67584 + idx]  = hlast;
        out[133120 + idx] = creg;
    }
    CLUSTER_SYNC();            // no CTA exits while peers may still own our smem
}

// ---------------- output projection ----------------
__global__ void logits_kernel(const float* __restrict__ hbase,
                              const float* __restrict__ W_out,
                              const float* __restrict__ b_out,
                              float* __restrict__ out_logits) {
    int b = blockIdx.x;
    int d = threadIdx.x >> 5;
    int lane = threadIdx.x & 31;
    const float* hr = hbase + (size_t)b * HH;
    const float* wr = W_out + (size_t)d * HH;
    float s = 0.f;
    #pragma unroll
    for (int k = lane; k < HH; k += 32) s += hr[k] * wr[k];
    #pragma unroll
    for (int o = 16; o; o >>= 1) s += __shfl_down_sync(0xffffffffu, s, o);
    if (lane == 0) out_logits[b * DOUT + d] = s + b_out[d];
}

// ---------------- launch ----------------
extern "C" void kernel_launch(void* const* d_in, const int* in_sizes, int n_in,
                              void* d_out, int out_size) {
    const float* x     = (const float*)d_in[0];
    const float* h0    = (const float*)d_in[1];
    const float* c0    = (const float*)d_in[2];
    const float* W_ih  = (const float*)d_in[3];
    const float* W_hh  = (const float*)d_in[4];
    const float* bias  = (const float*)d_in[5];
    const float* W_out = (const float*)d_in[6];
    const float* b_out = (const float*)d_in[7];
    float* out = (float*)d_out;

    static int cfg_done = 0;
    if (!cfg_done) {
        cudaFuncSetAttribute(lstm_kernel, cudaFuncAttributeMaxDynamicSharedMemorySize,
                             LSTM_SMEM);
        cudaFuncSetAttribute(xproj_kernel, cudaFuncAttributeMaxDynamicSharedMemorySize,
                             XP_SMEM);
        cfg_done = 1;
    }

    reorder_whh_kernel<<<HH, 256>>>(W_hh);
    reorder_wih_kernel<<<GG, 64>>>(W_ih, bias);

    xproj_kernel<<<dim3((BB_ * TT) / 64, GG / 128), 256, XP_SMEM>>>(x);

    lstm_kernel<<<NCTA, NT, LSTM_SMEM>>>(h0, c0, out);

    logits_kernel<<<BB_, 256>>>(out, W_out, b_out, out + 65536);
}